// round 14
// baseline (speedup 1.0000x reference)
#include <cuda_runtime.h>
#include <math.h>
#include <stdint.h>

#define N_NODES 100000
#define NE      1000000
#define DIM     64
#define TM      64           // edges per CTA in fused kernel
#define AST     68           // A tile row stride (floats): conflict-free

// ---------------- scratch (allocation-free rule) ----------------
__device__ float g_node_sum[(size_t)N_NODES * DIM];   // 25.6 MB
__device__ float g_deg[N_NODES];
__device__ int   g_is64;
__device__ float g_wfg[DIM];              // Wf @ Wg
__device__ float g_wbg[DIM];              // Wb @ Wg
__device__ float g_cb;                    // (bf+bb)@Wg + bg
__device__ float g_wfragF[2 * 8 * 32 * 8];  // fragment-ordered tf32 Wf
__device__ float g_wfragB[2 * 8 * 32 * 8];  // fragment-ordered tf32 Wb

// ---------------- dtype probe (proven round 3) ----------------
__global__ void detect_kernel(const int* __restrict__ idx32) {
    __shared__ int any_nonzero;
    if (threadIdx.x == 0) any_nonzero = 0;
    __syncthreads();
    int t = threadIdx.x;
    #pragma unroll
    for (int i = 0; i < 4; ++i) {
        int pos = 2 * (t + i * 256) + 1;
        if (idx32[pos] != 0) any_nonzero = 1;
    }
    __syncthreads();
    if (threadIdx.x == 0) g_is64 = any_nonzero ? 0 : 1;
}

__device__ __forceinline__ int load_index(const void* idx, long long pos, int is64) {
    long long r = is64 ? ((const long long*)idx)[pos]
                       : (long long)((const int*)idx)[pos];
    if (r < 0) r = 0;
    if (r >= N_NODES) r = N_NODES - 1;
    return (int)r;
}

__global__ void zero_kernel() {
    size_t i = (size_t)blockIdx.x * blockDim.x + threadIdx.x;
    float4 z = make_float4(0.f, 0.f, 0.f, 0.f);
    if (i < (size_t)N_NODES * DIM / 4)
        reinterpret_cast<float4*>(g_node_sum)[i] = z;
    if (i < N_NODES / 4)
        reinterpret_cast<float4*>(g_deg)[i] = z;
}

__device__ __forceinline__ float tf32r(float x) {
    uint32_t u;
    asm("cvt.rna.tf32.f32 %0, %1;" : "=r"(u) : "f"(x));
    return __uint_as_float(u);
}

// Prep: gate vectors + fragment-ordered tf32 weight arrays.
__global__ void prep_kernel(const float* __restrict__ Wf,
                            const float* __restrict__ Wb,
                            const float* __restrict__ bf,
                            const float* __restrict__ bb,
                            const float* __restrict__ Wg,
                            const float* __restrict__ bg) {
    int tid = threadIdx.x;                // 256
    if (tid < DIM) {
        float w, sf = 0.f, sb = 0.f;
        #pragma unroll 8
        for (int n = 0; n < DIM; ++n) {
            w = Wg[n];
            sf = fmaf(Wf[tid * DIM + n], w, sf);
            sb = fmaf(Wb[tid * DIM + n], w, sb);
        }
        g_wfg[tid] = sf;
        g_wbg[tid] = sb;
        if (tid == 0) {
            float c = 0.f;
            for (int n = 0; n < DIM; ++n) c = fmaf(bf[n] + bb[n], Wg[n], c);
            g_cb = c + bg[0];
        }
    }
    #pragma unroll
    for (int i = 0; i < 16; ++i) {
        int lin  = tid + i * 256;         // 0..4095
        int j    = lin & 7;
        int lane = (lin >> 3) & 31;
        int k0   = (lin >> 8) & 7;
        int nh   = lin >> 11;
        int tg = lane & 3, g = lane >> 2;
        int p = j & 1, nj = j >> 1;
        int k = k0 * 8 + tg + p * 4;
        int n = nh * 32 + nj * 8 + g;
        g_wfragF[lin] = tf32r(Wf[k * DIM + n]);
        g_wfragB[lin] = tf32r(Wb[k * DIM + n]);
    }
}

// ---------------- scatter (proven round 3) ----------------
__global__ void scatter_kernel(const float* __restrict__ emb,
                               const void* __restrict__ idx) {
    const int is64 = g_is64;
    int t = blockIdx.x * blockDim.x + threadIdx.x;
    int e = t >> 4;
    if (e >= NE) return;
    int q = t & 15;
    int u = load_index(idx, 2LL * e, is64);
    int v = load_index(idx, 2LL * e + 1, is64);
    float4 val = reinterpret_cast<const float4*>(emb)[e * 16 + q];
    float* pu = g_node_sum + (size_t)u * DIM + q * 4;
    float* pv = g_node_sum + (size_t)v * DIM + q * 4;
    asm volatile("red.global.add.v4.f32 [%0], {%1, %2, %3, %4};"
                 :: "l"(pu), "f"(val.x), "f"(val.y), "f"(val.z), "f"(val.w)
                 : "memory");
    asm volatile("red.global.add.v4.f32 [%0], {%1, %2, %3, %4};"
                 :: "l"(pv), "f"(val.x), "f"(val.y), "f"(val.z), "f"(val.w)
                 : "memory");
    if (q == 0) {
        atomicAdd(&g_deg[u], 1.0f);
        atomicAdd(&g_deg[v], 1.0f);
    }
}

// ---------------- mma helpers ----------------
__device__ __forceinline__ void mma8(float* d, const uint32_t* a, const uint32_t* b) {
    asm volatile(
        "mma.sync.aligned.m16n8k8.row.col.f32.tf32.tf32.f32 "
        "{%0,%1,%2,%3}, {%4,%5,%6,%7}, {%8,%9}, {%0,%1,%2,%3};"
        : "+f"(d[0]), "+f"(d[1]), "+f"(d[2]), "+f"(d[3])
        : "r"(a[0]), "r"(a[1]), "r"(a[2]), "r"(a[3]), "r"(b[0]), "r"(b[1]));
}
__device__ __forceinline__ void ldm4(uint32_t* r, uint32_t addr) {
    asm volatile("ldmatrix.sync.aligned.m8n8.x4.shared.b16 {%0,%1,%2,%3}, [%4];"
                 : "=r"(r[0]), "=r"(r[1]), "=r"(r[2]), "=r"(r[3]) : "r"(addr));
}
__device__ __forceinline__ uint32_t smem_u32(const void* p) {
    uint32_t a;
    asm("{ .reg .u64 t; cvta.to.shared.u64 t, %1; cvt.u32.u64 %0, t; }" : "=r"(a) : "l"(p));
    return a;
}

// ---------------- fused kernel: 64 edges/CTA, 128 thr, 5 CTAs/SM ----------------
// smem floats: sAu[64][AST], sAv[64][AST], sBf[64], sBb[64], sG[64] = 35584 B
__global__ __launch_bounds__(128, 5)
void fused_kernel(const float* __restrict__ emb,
                  const float* __restrict__ bf, const float* __restrict__ bb,
                  const void* __restrict__ idx,
                  float* __restrict__ out) {
    extern __shared__ float sm[];
    float* sAu = sm;                       // reused as output staging tile
    float* sAv = sAu + TM * AST;
    float* sBf = sAv + TM * AST;
    float* sBb = sBf + DIM;
    float* sG  = sBb + DIM;

    const int tid  = threadIdx.x;
    const int lane = tid & 31;
    const int wid  = tid >> 5;
    const int is64 = g_is64;

    if (tid < DIM) {
        sBf[tid] = bf[tid];
        sBb[tid] = bb[tid];
    }

    // Hoist index/degree/scale chain for BOTH passes (removes the serial
    // idx->deg dependency from pass 1's critical path).
    const int m  = tid & 3;
    const int qe = tid >> 2;               // 0..31
    int uu[2], vv[2];
    float ssu[2], ssv[2];
    #pragma unroll
    for (int pass = 0; pass < 2; ++pass) {
        int e = blockIdx.x * TM + pass * 32 + qe;
        uu[pass] = load_index(idx, 2LL * e, is64);
        vv[pass] = load_index(idx, 2LL * e + 1, is64);
    }
    #pragma unroll
    for (int pass = 0; pass < 2; ++pass) {
        float du = g_deg[uu[pass]], dv = g_deg[vv[pass]];
        ssu[pass] = (du > 1.f) ? 1.f / (du - 1.f) : 0.f;
        ssv[pass] = (dv > 1.f) ? 1.f / (dv - 1.f) : 0.f;
    }

    // Build A tiles + per-edge gate. Quad-per-edge coalesced gather (proven R12).
    #pragma unroll
    for (int pass = 0; pass < 2; ++pass) {
        int le = pass * 32 + qe;
        int e  = blockIdx.x * TM + le;
        float su = ssu[pass], sv = ssv[pass];
        const float4* pe = reinterpret_cast<const float4*>(emb + (size_t)e * DIM);
        const float4* pu = reinterpret_cast<const float4*>(g_node_sum + (size_t)uu[pass] * DIM);
        const float4* pv = reinterpret_cast<const float4*>(g_node_sum + (size_t)vv[pass] * DIM);
        const float4* pwf = reinterpret_cast<const float4*>(g_wfg);
        const float4* pwb = reinterpret_cast<const float4*>(g_wbg);

        float4 em[4], nu[4], nv[4];
        #pragma unroll
        for (int i = 0; i < 4; ++i) {
            int cc = i * 4 + m;
            em[i] = pe[cc];
            nu[i] = pu[cc];
            nv[i] = pv[cc];
        }

        float t = 0.f;
        #pragma unroll
        for (int i = 0; i < 4; ++i) {
            int cc = i * 4 + m;
            float4 wf4 = pwf[cc], wb4 = pwb[cc];
            float4 au, av;
            au.x = (nu[i].x - em[i].x) * su; au.y = (nu[i].y - em[i].y) * su;
            au.z = (nu[i].z - em[i].z) * su; au.w = (nu[i].w - em[i].w) * su;
            av.x = (nv[i].x - em[i].x) * sv; av.y = (nv[i].y - em[i].y) * sv;
            av.z = (nv[i].z - em[i].z) * sv; av.w = (nv[i].w - em[i].w) * sv;
            t = fmaf(au.x, wf4.x, t); t = fmaf(au.y, wf4.y, t);
            t = fmaf(au.z, wf4.z, t); t = fmaf(au.w, wf4.w, t);
            t = fmaf(av.x, wb4.x, t); t = fmaf(av.y, wb4.y, t);
            t = fmaf(av.z, wb4.z, t); t = fmaf(av.w, wb4.w, t);
            float4 auq = make_float4(tf32r(au.x), tf32r(au.y), tf32r(au.z), tf32r(au.w));
            float4 avq = make_float4(tf32r(av.x), tf32r(av.y), tf32r(av.z), tf32r(av.w));
            *reinterpret_cast<float4*>(sAu + le * AST + cc * 4) = auq;
            *reinterpret_cast<float4*>(sAv + le * AST + cc * 4) = avq;
        }
        t += __shfl_xor_sync(0xffffffffu, t, 2);
        t += __shfl_xor_sync(0xffffffffu, t, 1);
        if (m == 0) {
            float gg = 1.f / (1.f + expf(-(t + g_cb)));
            sG[le] = gg;
        }
    }
    __syncthreads();

    // Mainloop: warp tile 32 edges x 32 cols, both GEMMs.
    const int g  = lane >> 2;
    const int tg = lane & 3;
    const int m0 = (wid >> 1) * 32;
    const int nh = wid & 1;

    const int lrow  = lane & 15;
    const int lkoff = (lane >> 4) * 4;
    uint32_t aaddrU0 = smem_u32(sAu + (m0 + lrow) * AST + lkoff);
    uint32_t aaddrU1 = smem_u32(sAu + (m0 + 16 + lrow) * AST + lkoff);
    uint32_t aaddrV0 = smem_u32(sAv + (m0 + lrow) * AST + lkoff);
    uint32_t aaddrV1 = smem_u32(sAv + (m0 + 16 + lrow) * AST + lkoff);

    const float4* pF = reinterpret_cast<const float4*>(g_wfragF) + (nh * 8 * 32 + lane) * 2;
    const float4* pB = reinterpret_cast<const float4*>(g_wfragB) + (nh * 8 * 32 + lane) * 2;

    float dU[2][4][4] = {};
    float dV[2][4][4] = {};

    #pragma unroll
    for (int k0 = 0; k0 < 8; ++k0) {
        uint32_t aU[2][4], aV[2][4];
        ldm4(aU[0], aaddrU0 + k0 * 32);
        ldm4(aU[1], aaddrU1 + k0 * 32);
        ldm4(aV[0], aaddrV0 + k0 * 32);
        ldm4(aV[1], aaddrV1 + k0 * 32);

        float4 f0 = pF[k0 * 64 + 0], f1 = pF[k0 * 64 + 1];
        float4 b0 = pB[k0 * 64 + 0], b1 = pB[k0 * 64 + 1];
        uint32_t bF[4][2] = {
            {__float_as_uint(f0.x), __float_as_uint(f0.y)},
            {__float_as_uint(f0.z), __float_as_uint(f0.w)},
            {__float_as_uint(f1.x), __float_as_uint(f1.y)},
            {__float_as_uint(f1.z), __float_as_uint(f1.w)}};
        uint32_t bB[4][2] = {
            {__float_as_uint(b0.x), __float_as_uint(b0.y)},
            {__float_as_uint(b0.z), __float_as_uint(b0.w)},
            {__float_as_uint(b1.x), __float_as_uint(b1.y)},
            {__float_as_uint(b1.z), __float_as_uint(b1.w)}};

        #pragma unroll
        for (int nj = 0; nj < 4; ++nj) {
            mma8(dU[0][nj], aU[0], bF[nj]);
            mma8(dU[1][nj], aU[1], bF[nj]);
            mma8(dV[0][nj], aV[0], bB[nj]);
            mma8(dV[1][nj], aV[1], bB[nj]);
        }
    }

    // Blend in registers, stage the 64x64 output tile in smem (reuse sAu,
    // stride AST keeps the fragment STS pattern conflict-free), then write
    // out with fully-coalesced STG.128.
    __syncthreads();                       // all ldmatrix reads of sAu/sAv done
    #pragma unroll
    for (int mi = 0; mi < 2; ++mi) {
        int r0 = m0 + mi * 16 + g;
        float g0 = sG[r0], g1 = sG[r0 + 8];
        float h0 = 1.f - g0, h1 = 1.f - g1;
        #pragma unroll
        for (int nj = 0; nj < 4; ++nj) {
            int col = nh * 32 + nj * 8 + 2 * tg;
            float bf0 = sBf[col], bf1 = sBf[col + 1];
            float bb0 = sBb[col], bb1 = sBb[col + 1];
            float2 o;
            o.x = g0 * (dU[mi][nj][0] + bf0) + h0 * (dV[mi][nj][0] + bb0);
            o.y = g0 * (dU[mi][nj][1] + bf1) + h0 * (dV[mi][nj][1] + bb1);
            *reinterpret_cast<float2*>(sAu + r0 * AST + col) = o;
            o.x = g1 * (dU[mi][nj][2] + bf0) + h1 * (dV[mi][nj][2] + bb0);
            o.y = g1 * (dU[mi][nj][3] + bf1) + h1 * (dV[mi][nj][3] + bb1);
            *reinterpret_cast<float2*>(sAu + (r0 + 8) * AST + col) = o;
        }
    }
    __syncthreads();

    // Coalesced writeback: 1024 float4s, lane-consecutive => 128B/instr STG.
    {
        const size_t obase = (size_t)blockIdx.x * TM * DIM;
        #pragma unroll
        for (int j = 0; j < 8; ++j) {
            int fidx = tid + j * 128;          // 0..1023
            int row  = fidx >> 4;
            int c4   = fidx & 15;
            float4 v = *reinterpret_cast<const float4*>(sAu + row * AST + c4 * 4);
            reinterpret_cast<float4*>(out + obase)[fidx] = v;
        }
    }
}

extern "C" void kernel_launch(void* const* d_in, const int* in_sizes, int n_in,
                              void* d_out, int out_size) {
    const float* emb = (const float*)d_in[0];
    const float* Wf  = (const float*)d_in[1];
    const float* bf  = (const float*)d_in[2];
    const float* Wb  = (const float*)d_in[3];
    const float* bb  = (const float*)d_in[4];
    const float* Wg  = (const float*)d_in[5];
    const float* bg  = (const float*)d_in[6];
    const void*  idx = d_in[7];
    float* out = (float*)d_out;

    (void)in_sizes; (void)n_in; (void)out_size;

    detect_kernel<<<1, 256>>>((const int*)idx);

    int zthreads = (N_NODES * DIM) / 4;
    zero_kernel<<<(zthreads + 255) / 256, 256>>>();

    prep_kernel<<<1, 256>>>(Wf, Wb, bf, bb, Wg, bg);

    int sthreads = NE * 16;
    scatter_kernel<<<(sthreads + 255) / 256, 256>>>(emb, idx);

    int smem = (2 * TM * AST + 2 * DIM + TM) * (int)sizeof(float);   // 35584
    cudaFuncSetAttribute(fused_kernel,
                         cudaFuncAttributeMaxDynamicSharedMemorySize, smem);
    fused_kernel<<<NE / TM, 128, smem>>>(emb, bf, bb, idx, out);
}

// round 15
// speedup vs baseline: 1.0413x; 1.0413x over previous
#include <cuda_runtime.h>
#include <math.h>
#include <stdint.h>

#define N_NODES 100000
#define NE      1000000
#define DIM     64
#define TM      64           // edges per CTA in fused kernel
#define AST     68           // A tile row stride (floats): conflict-free

// ---------------- scratch (allocation-free rule) ----------------
__device__ float g_node_sum[(size_t)N_NODES * DIM];   // 25.6 MB
__device__ float g_deg[N_NODES];
__device__ int   g_is64;
__device__ float g_wfg[DIM];              // Wf @ Wg
__device__ float g_wbg[DIM];              // Wb @ Wg
__device__ float g_cb;                    // (bf+bb)@Wg + bg
__device__ float g_wfragF[2 * 8 * 32 * 8];  // fragment-ordered tf32 Wf
__device__ float g_wfragB[2 * 8 * 32 * 8];  // fragment-ordered tf32 Wb

// ---------------- dtype probe (proven round 3) ----------------
__global__ void detect_kernel(const int* __restrict__ idx32) {
    __shared__ int any_nonzero;
    if (threadIdx.x == 0) any_nonzero = 0;
    __syncthreads();
    int t = threadIdx.x;
    #pragma unroll
    for (int i = 0; i < 4; ++i) {
        int pos = 2 * (t + i * 256) + 1;
        if (idx32[pos] != 0) any_nonzero = 1;
    }
    __syncthreads();
    if (threadIdx.x == 0) g_is64 = any_nonzero ? 0 : 1;
}

__device__ __forceinline__ int load_index(const void* idx, long long pos, int is64) {
    long long r = is64 ? ((const long long*)idx)[pos]
                       : (long long)((const int*)idx)[pos];
    if (r < 0) r = 0;
    if (r >= N_NODES) r = N_NODES - 1;
    return (int)r;
}

__global__ void zero_kernel() {
    size_t i = (size_t)blockIdx.x * blockDim.x + threadIdx.x;
    float4 z = make_float4(0.f, 0.f, 0.f, 0.f);
    if (i < (size_t)N_NODES * DIM / 4)
        reinterpret_cast<float4*>(g_node_sum)[i] = z;
    if (i < N_NODES / 4)
        reinterpret_cast<float4*>(g_deg)[i] = z;
}

__device__ __forceinline__ float tf32r(float x) {
    uint32_t u;
    asm("cvt.rna.tf32.f32 %0, %1;" : "=r"(u) : "f"(x));
    return __uint_as_float(u);
}

// Prep: gate vectors + fragment-ordered tf32 weight arrays.
__global__ void prep_kernel(const float* __restrict__ Wf,
                            const float* __restrict__ Wb,
                            const float* __restrict__ bf,
                            const float* __restrict__ bb,
                            const float* __restrict__ Wg,
                            const float* __restrict__ bg) {
    int tid = threadIdx.x;                // 256
    if (tid < DIM) {
        float w, sf = 0.f, sb = 0.f;
        #pragma unroll 8
        for (int n = 0; n < DIM; ++n) {
            w = Wg[n];
            sf = fmaf(Wf[tid * DIM + n], w, sf);
            sb = fmaf(Wb[tid * DIM + n], w, sb);
        }
        g_wfg[tid] = sf;
        g_wbg[tid] = sb;
        if (tid == 0) {
            float c = 0.f;
            for (int n = 0; n < DIM; ++n) c = fmaf(bf[n] + bb[n], Wg[n], c);
            g_cb = c + bg[0];
        }
    }
    #pragma unroll
    for (int i = 0; i < 16; ++i) {
        int lin  = tid + i * 256;         // 0..4095
        int j    = lin & 7;
        int lane = (lin >> 3) & 31;
        int k0   = (lin >> 8) & 7;
        int nh   = lin >> 11;
        int tg = lane & 3, g = lane >> 2;
        int p = j & 1, nj = j >> 1;
        int k = k0 * 8 + tg + p * 4;
        int n = nh * 32 + nj * 8 + g;
        g_wfragF[lin] = tf32r(Wf[k * DIM + n]);
        g_wfragB[lin] = tf32r(Wb[k * DIM + n]);
    }
}

// ---------------- scatter (proven round 3; emb via evict-first loads) ----------------
__global__ void scatter_kernel(const float* __restrict__ emb,
                               const void* __restrict__ idx) {
    const int is64 = g_is64;
    int t = blockIdx.x * blockDim.x + threadIdx.x;
    int e = t >> 4;
    if (e >= NE) return;
    int q = t & 15;
    int u = load_index(idx, 2LL * e, is64);
    int v = load_index(idx, 2LL * e + 1, is64);
    float4 val = __ldcs(reinterpret_cast<const float4*>(emb) + e * 16 + q);
    float* pu = g_node_sum + (size_t)u * DIM + q * 4;
    float* pv = g_node_sum + (size_t)v * DIM + q * 4;
    asm volatile("red.global.add.v4.f32 [%0], {%1, %2, %3, %4};"
                 :: "l"(pu), "f"(val.x), "f"(val.y), "f"(val.z), "f"(val.w)
                 : "memory");
    asm volatile("red.global.add.v4.f32 [%0], {%1, %2, %3, %4};"
                 :: "l"(pv), "f"(val.x), "f"(val.y), "f"(val.z), "f"(val.w)
                 : "memory");
    if (q == 0) {
        atomicAdd(&g_deg[u], 1.0f);
        atomicAdd(&g_deg[v], 1.0f);
    }
}

// ---------------- mma helpers ----------------
__device__ __forceinline__ void mma8(float* d, const uint32_t* a, const uint32_t* b) {
    asm volatile(
        "mma.sync.aligned.m16n8k8.row.col.f32.tf32.tf32.f32 "
        "{%0,%1,%2,%3}, {%4,%5,%6,%7}, {%8,%9}, {%0,%1,%2,%3};"
        : "+f"(d[0]), "+f"(d[1]), "+f"(d[2]), "+f"(d[3])
        : "r"(a[0]), "r"(a[1]), "r"(a[2]), "r"(a[3]), "r"(b[0]), "r"(b[1]));
}
__device__ __forceinline__ void ldm4(uint32_t* r, uint32_t addr) {
    asm volatile("ldmatrix.sync.aligned.m8n8.x4.shared.b16 {%0,%1,%2,%3}, [%4];"
                 : "=r"(r[0]), "=r"(r[1]), "=r"(r[2]), "=r"(r[3]) : "r"(addr));
}
__device__ __forceinline__ uint32_t smem_u32(const void* p) {
    uint32_t a;
    asm("{ .reg .u64 t; cvta.to.shared.u64 t, %1; cvt.u32.u64 %0, t; }" : "=r"(a) : "l"(p));
    return a;
}

// ---------------- fused kernel: 64 edges/CTA, 128 thr, 5 CTAs/SM ----------------
// smem floats: sAu[64][AST], sAv[64][AST], sBf[64], sBb[64], sG[64] = 35584 B
__global__ __launch_bounds__(128, 5)
void fused_kernel(const float* __restrict__ emb,
                  const float* __restrict__ bf, const float* __restrict__ bb,
                  const void* __restrict__ idx,
                  float* __restrict__ out) {
    extern __shared__ float sm[];
    float* sAu = sm;
    float* sAv = sAu + TM * AST;
    float* sBf = sAv + TM * AST;
    float* sBb = sBf + DIM;
    float* sG  = sBb + DIM;

    const int tid  = threadIdx.x;
    const int lane = tid & 31;
    const int wid  = tid >> 5;
    const int is64 = g_is64;

    if (tid < DIM) {
        sBf[tid] = bf[tid];
        sBb[tid] = bb[tid];
    }

    // Hoisted index/degree/scale chain for both passes (kept from R13/R14).
    const int m  = tid & 3;
    const int qe = tid >> 2;               // 0..31
    int uu[2], vv[2];
    float ssu[2], ssv[2];
    #pragma unroll
    for (int pass = 0; pass < 2; ++pass) {
        int e = blockIdx.x * TM + pass * 32 + qe;
        uu[pass] = load_index(idx, 2LL * e, is64);
        vv[pass] = load_index(idx, 2LL * e + 1, is64);
    }
    #pragma unroll
    for (int pass = 0; pass < 2; ++pass) {
        float du = g_deg[uu[pass]], dv = g_deg[vv[pass]];
        ssu[pass] = (du > 1.f) ? 1.f / (du - 1.f) : 0.f;
        ssv[pass] = (dv > 1.f) ? 1.f / (dv - 1.f) : 0.f;
    }

    // Build A tiles + per-edge gate. Quad-per-edge coalesced gather (proven R12).
    // emb read with evict-first (__ldcs): pure streaming, keep L2 for node_sum.
    #pragma unroll
    for (int pass = 0; pass < 2; ++pass) {
        int le = pass * 32 + qe;
        int e  = blockIdx.x * TM + le;
        float su = ssu[pass], sv = ssv[pass];
        const float4* pe = reinterpret_cast<const float4*>(emb + (size_t)e * DIM);
        const float4* pu = reinterpret_cast<const float4*>(g_node_sum + (size_t)uu[pass] * DIM);
        const float4* pv = reinterpret_cast<const float4*>(g_node_sum + (size_t)vv[pass] * DIM);
        const float4* pwf = reinterpret_cast<const float4*>(g_wfg);
        const float4* pwb = reinterpret_cast<const float4*>(g_wbg);

        float4 em[4], nu[4], nv[4];
        #pragma unroll
        for (int i = 0; i < 4; ++i) {
            int cc = i * 4 + m;
            em[i] = __ldcs(pe + cc);
            nu[i] = pu[cc];
            nv[i] = pv[cc];
        }

        float t = 0.f;
        #pragma unroll
        for (int i = 0; i < 4; ++i) {
            int cc = i * 4 + m;
            float4 wf4 = pwf[cc], wb4 = pwb[cc];
            float4 au, av;
            au.x = (nu[i].x - em[i].x) * su; au.y = (nu[i].y - em[i].y) * su;
            au.z = (nu[i].z - em[i].z) * su; au.w = (nu[i].w - em[i].w) * su;
            av.x = (nv[i].x - em[i].x) * sv; av.y = (nv[i].y - em[i].y) * sv;
            av.z = (nv[i].z - em[i].z) * sv; av.w = (nv[i].w - em[i].w) * sv;
            t = fmaf(au.x, wf4.x, t); t = fmaf(au.y, wf4.y, t);
            t = fmaf(au.z, wf4.z, t); t = fmaf(au.w, wf4.w, t);
            t = fmaf(av.x, wb4.x, t); t = fmaf(av.y, wb4.y, t);
            t = fmaf(av.z, wb4.z, t); t = fmaf(av.w, wb4.w, t);
            float4 auq = make_float4(tf32r(au.x), tf32r(au.y), tf32r(au.z), tf32r(au.w));
            float4 avq = make_float4(tf32r(av.x), tf32r(av.y), tf32r(av.z), tf32r(av.w));
            *reinterpret_cast<float4*>(sAu + le * AST + cc * 4) = auq;
            *reinterpret_cast<float4*>(sAv + le * AST + cc * 4) = avq;
        }
        t += __shfl_xor_sync(0xffffffffu, t, 2);
        t += __shfl_xor_sync(0xffffffffu, t, 1);
        if (m == 0) {
            float gg = 1.f / (1.f + expf(-(t + g_cb)));
            sG[le] = gg;
        }
    }
    __syncthreads();        // the only barrier

    // Mainloop: warp tile 32 edges x 32 cols, both GEMMs (proven R11/R12).
    const int g  = lane >> 2;
    const int tg = lane & 3;
    const int m0 = (wid >> 1) * 32;
    const int nh = wid & 1;

    const int lrow  = lane & 15;
    const int lkoff = (lane >> 4) * 4;
    uint32_t aaddrU0 = smem_u32(sAu + (m0 + lrow) * AST + lkoff);
    uint32_t aaddrU1 = smem_u32(sAu + (m0 + 16 + lrow) * AST + lkoff);
    uint32_t aaddrV0 = smem_u32(sAv + (m0 + lrow) * AST + lkoff);
    uint32_t aaddrV1 = smem_u32(sAv + (m0 + 16 + lrow) * AST + lkoff);

    const float4* pF = reinterpret_cast<const float4*>(g_wfragF) + (nh * 8 * 32 + lane) * 2;
    const float4* pB = reinterpret_cast<const float4*>(g_wfragB) + (nh * 8 * 32 + lane) * 2;

    float dU[2][4][4] = {};
    float dV[2][4][4] = {};

    #pragma unroll
    for (int k0 = 0; k0 < 8; ++k0) {
        uint32_t aU[2][4], aV[2][4];
        ldm4(aU[0], aaddrU0 + k0 * 32);
        ldm4(aU[1], aaddrU1 + k0 * 32);
        ldm4(aV[0], aaddrV0 + k0 * 32);
        ldm4(aV[1], aaddrV1 + k0 * 32);

        float4 f0 = pF[k0 * 64 + 0], f1 = pF[k0 * 64 + 1];
        float4 b0 = pB[k0 * 64 + 0], b1 = pB[k0 * 64 + 1];
        uint32_t bF[4][2] = {
            {__float_as_uint(f0.x), __float_as_uint(f0.y)},
            {__float_as_uint(f0.z), __float_as_uint(f0.w)},
            {__float_as_uint(f1.x), __float_as_uint(f1.y)},
            {__float_as_uint(f1.z), __float_as_uint(f1.w)}};
        uint32_t bB[4][2] = {
            {__float_as_uint(b0.x), __float_as_uint(b0.y)},
            {__float_as_uint(b0.z), __float_as_uint(b0.w)},
            {__float_as_uint(b1.x), __float_as_uint(b1.y)},
            {__float_as_uint(b1.z), __float_as_uint(b1.w)}};

        #pragma unroll
        for (int nj = 0; nj < 4; ++nj) {
            mma8(dU[0][nj], aU[0], bF[nj]);
            mma8(dU[1][nj], aU[1], bF[nj]);
            mma8(dV[0][nj], aV[0], bB[nj]);
            mma8(dV[1][nj], aV[1], bB[nj]);
        }
    }

    // Epilogue directly from fragments (R12 proven form), stores evict-first.
    const int ebase = blockIdx.x * TM;
    #pragma unroll
    for (int mi = 0; mi < 2; ++mi) {
        int r0 = m0 + mi * 16 + g;
        float g0 = sG[r0], g1 = sG[r0 + 8];
        float h0 = 1.f - g0, h1 = 1.f - g1;
        #pragma unroll
        for (int nj = 0; nj < 4; ++nj) {
            int col = nh * 32 + nj * 8 + 2 * tg;
            float bf0 = sBf[col], bf1 = sBf[col + 1];
            float bb0 = sBb[col], bb1 = sBb[col + 1];
            float2 o;
            o.x = g0 * (dU[mi][nj][0] + bf0) + h0 * (dV[mi][nj][0] + bb0);
            o.y = g0 * (dU[mi][nj][1] + bf1) + h0 * (dV[mi][nj][1] + bb1);
            __stcs(reinterpret_cast<float2*>(out + (size_t)(ebase + r0) * DIM + col), o);
            o.x = g1 * (dU[mi][nj][2] + bf0) + h1 * (dV[mi][nj][2] + bb0);
            o.y = g1 * (dU[mi][nj][3] + bf1) + h1 * (dV[mi][nj][3] + bb1);
            __stcs(reinterpret_cast<float2*>(out + (size_t)(ebase + r0 + 8) * DIM + col), o);
        }
    }
}

extern "C" void kernel_launch(void* const* d_in, const int* in_sizes, int n_in,
                              void* d_out, int out_size) {
    const float* emb = (const float*)d_in[0];
    const float* Wf  = (const float*)d_in[1];
    const float* bf  = (const float*)d_in[2];
    const float* Wb  = (const float*)d_in[3];
    const float* bb  = (const float*)d_in[4];
    const float* Wg  = (const float*)d_in[5];
    const float* bg  = (const float*)d_in[6];
    const void*  idx = d_in[7];
    float* out = (float*)d_out;

    (void)in_sizes; (void)n_in; (void)out_size;

    detect_kernel<<<1, 256>>>((const int*)idx);

    int zthreads = (N_NODES * DIM) / 4;
    zero_kernel<<<(zthreads + 255) / 256, 256>>>();

    prep_kernel<<<1, 256>>>(Wf, Wb, bf, bb, Wg, bg);

    int sthreads = NE * 16;
    scatter_kernel<<<(sthreads + 255) / 256, 256>>>(emb, idx);

    int smem = (2 * TM * AST + 2 * DIM + TM) * (int)sizeof(float);   // 35584
    cudaFuncSetAttribute(fused_kernel,
                         cudaFuncAttributeMaxDynamicSharedMemorySize, smem);
    fused_kernel<<<NE / TM, 128, smem>>>(emb, bf, bb, idx, out);
}